// round 7
// baseline (speedup 1.0000x reference)
#include <cuda_runtime.h>
#include <cuda_bf16.h>
#include <cstdint>

#define XDIM 1024
#define KD 64            // output dim (N)
#define KC 64            // k-chunk
#define NCH (XDIM / KC)  // 16
#define ROWS 128
#define THREADS 256

#define VS_STRIDE 72                        // bf16 units per n-row (pad 64->72)
#define VS_BYTES (KD * VS_STRIDE * 2)       // 9216 per (hi|lo) tile
#define STAGE_BYTES (2 * VS_BYTES)          // 18432
#define OFF_W 0
#define OFF_V 4096
#define SMEM_BYTES (OFF_V + 2 * STAGE_BYTES)   // 40960

__device__ float g_w[XDIM];                               // w[i] = sum_k V[i][k]^2
__device__ __align__(16) unsigned short g_vth[KD * XDIM]; // vT_hi[n][i]
__device__ __align__(16) unsigned short g_vtl[KD * XDIM]; // vT_lo[n][i]

__device__ __forceinline__ unsigned smaddr(const void* p) {
    return (unsigned)__cvta_generic_to_shared(p);
}
__device__ __forceinline__ void cp16(unsigned dst, const void* src) {
    asm volatile("cp.async.cg.shared.global [%0], [%1], 16;" :: "r"(dst), "l"(src));
}
__device__ __forceinline__ unsigned packbf(float a, float b) {
    unsigned short ha = __bfloat16_as_ushort(__float2bfloat16(a));
    unsigned short hb = __bfloat16_as_ushort(__float2bfloat16(b));
    return (unsigned)ha | ((unsigned)hb << 16);
}
__device__ __forceinline__ void split2(float2 f, unsigned& hi, unsigned& lo) {
    __nv_bfloat16 hx = __float2bfloat16(f.x);
    __nv_bfloat16 hy = __float2bfloat16(f.y);
    hi = (unsigned)__bfloat16_as_ushort(hx) | ((unsigned)__bfloat16_as_ushort(hy) << 16);
    lo = packbf(f.x - __bfloat162float(hx), f.y - __bfloat162float(hy));
}
__device__ __forceinline__ void mma16816(float* d, const unsigned* a,
                                         unsigned b0, unsigned b1) {
    asm volatile(
        "mma.sync.aligned.m16n8k16.row.col.f32.bf16.bf16.f32 "
        "{%0,%1,%2,%3}, {%4,%5,%6,%7}, {%8,%9}, {%0,%1,%2,%3};"
        : "+f"(d[0]), "+f"(d[1]), "+f"(d[2]), "+f"(d[3])
        : "r"(a[0]), "r"(a[1]), "r"(a[2]), "r"(a[3]), "r"(b0), "r"(b1));
}
__device__ __forceinline__ void split1(float f, unsigned short& hh, unsigned short& ll) {
    __nv_bfloat16 bh = __float2bfloat16(f);
    hh = __bfloat16_as_ushort(bh);
    ll = __bfloat16_as_ushort(__float2bfloat16(f - __bfloat162float(bh)));
}

// ---------------- prep: transpose + split V, compute w ----------------
__global__ void prep_tc(const float* __restrict__ v) {
    __shared__ unsigned short th[KD][72];
    __shared__ unsigned short tl[KD][72];
    const int b = blockIdx.x;               // 16 blocks, i0 = b*64
    const int t = threadIdx.x;              // 256
    const int il = t >> 2, cq = t & 3;
    const int i = b * 64 + il;

    float wq = 0.f;
    #pragma unroll
    for (int j = 0; j < 4; j++) {
        float4 f = *(const float4*)(v + (size_t)i * KD + cq * 16 + j * 4);
        wq = fmaf(f.x, f.x, wq); wq = fmaf(f.y, f.y, wq);
        wq = fmaf(f.z, f.z, wq); wq = fmaf(f.w, f.w, wq);
        float vals[4] = {f.x, f.y, f.z, f.w};
        #pragma unroll
        for (int u = 0; u < 4; u++) {
            int n = cq * 16 + j * 4 + u;
            split1(vals[u], th[n][il], tl[n][il]);
        }
    }
    wq += __shfl_xor_sync(0xffffffffu, wq, 1);
    wq += __shfl_xor_sync(0xffffffffu, wq, 2);
    if (cq == 0) g_w[i] = wq;
    __syncthreads();

    const int n = t >> 2, un = t & 3;
    #pragma unroll
    for (int rr = 0; rr < 2; rr++) {
        int u = un + rr * 4;
        const unsigned short* ph = &th[n][u * 8];
        const unsigned short* pl = &tl[n][u * 8];
        uint4 oh, ol;
        oh.x = (unsigned)ph[0] | ((unsigned)ph[1] << 16);
        oh.y = (unsigned)ph[2] | ((unsigned)ph[3] << 16);
        oh.z = (unsigned)ph[4] | ((unsigned)ph[5] << 16);
        oh.w = (unsigned)ph[6] | ((unsigned)ph[7] << 16);
        ol.x = (unsigned)pl[0] | ((unsigned)pl[1] << 16);
        ol.y = (unsigned)pl[2] | ((unsigned)pl[3] << 16);
        ol.z = (unsigned)pl[4] | ((unsigned)pl[5] << 16);
        ol.w = (unsigned)pl[6] | ((unsigned)pl[7] << 16);
        *(uint4*)(g_vth + (size_t)n * XDIM + b * 64 + u * 8) = oh;
        *(uint4*)(g_vtl + (size_t)n * XDIM + b * 64 + u * 8) = ol;
    }
}

// ---------------- main: split-bf16 mma.sync GEMM, x+V double-pipelined ----------------
__global__ __launch_bounds__(THREADS, 1)
void fm_mma(const float* __restrict__ x, float* __restrict__ out) {
    extern __shared__ __align__(128) char smem[];
    const unsigned sbase = smaddr(smem);
    const int tid = threadIdx.x;
    const int warp = tid >> 5;
    const int lane = tid & 31;
    const int g = lane >> 2;
    const int t = lane & 3;
    const size_t row0w = (size_t)blockIdx.x * ROWS + warp * 16;

    *(float4*)(smem + OFF_W + tid * 16) = *(const float4*)(g_w + tid * 4);

    float acc[8][4];
    #pragma unroll
    for (int nf = 0; nf < 8; nf++)
        #pragma unroll
        for (int j = 0; j < 4; j++) acc[nf][j] = 0.f;
    float qg = 0.f, qg8 = 0.f;

    float2 xra[16], xrb[16];

    auto ldx = [&](int c, float2 (&xr)[16]) {
        const float* xg = x + row0w * XDIM + c * KC;
        #pragma unroll
        for (int k16 = 0; k16 < 4; k16++) {
            const float* p = xg + k16 * 16 + 2 * t;
            xr[k16 * 4 + 0] = *(const float2*)(p + (size_t)g * XDIM);
            xr[k16 * 4 + 1] = *(const float2*)(p + (size_t)(g + 8) * XDIM);
            xr[k16 * 4 + 2] = *(const float2*)(p + (size_t)g * XDIM + 8);
            xr[k16 * 4 + 3] = *(const float2*)(p + (size_t)(g + 8) * XDIM + 8);
        }
    };

    auto load_chunk = [&](int c, int s) {
        unsigned vh = sbase + OFF_V + s * STAGE_BYTES;
        unsigned vl = vh + VS_BYTES;
        #pragma unroll
        for (int nn = 0; nn < 2; nn++) {
            int u = tid + nn * THREADS;
            int row = u >> 3, o = u & 7;
            cp16(vh + row * (VS_STRIDE * 2) + o * 16,
                 g_vth + (size_t)row * XDIM + c * KC + o * 8);
        }
        #pragma unroll
        for (int nn = 0; nn < 2; nn++) {
            int u = tid + nn * THREADS;
            int row = u >> 3, o = u & 7;
            cp16(vl + row * (VS_STRIDE * 2) + o * 16,
                 g_vtl + (size_t)row * XDIM + c * KC + o * 8);
        }
        asm volatile("cp.async.commit_group;");
    };

    auto compute_chunk = [&](int c, int s, float2 (&xr)[16]) {
        const char* vsh = smem + OFF_V + s * STAGE_BYTES;
        const char* vsl = vsh + VS_BYTES;
        const float* wsm = (const float*)(smem + OFF_W) + c * KC;
        #pragma unroll
        for (int k16 = 0; k16 < 4; k16++) {
            float2 x0 = xr[k16 * 4 + 0], x1 = xr[k16 * 4 + 1];
            float2 x2 = xr[k16 * 4 + 2], x3 = xr[k16 * 4 + 3];
            float2 w0 = *(const float2*)(wsm + k16 * 16 + 2 * t);
            float2 w1 = *(const float2*)(wsm + k16 * 16 + 2 * t + 8);
            qg  = fmaf(x0.x * x0.x, w0.x, qg);
            qg  = fmaf(x0.y * x0.y, w0.y, qg);
            qg  = fmaf(x2.x * x2.x, w1.x, qg);
            qg  = fmaf(x2.y * x2.y, w1.y, qg);
            qg8 = fmaf(x1.x * x1.x, w0.x, qg8);
            qg8 = fmaf(x1.y * x1.y, w0.y, qg8);
            qg8 = fmaf(x3.x * x3.x, w1.x, qg8);
            qg8 = fmaf(x3.y * x3.y, w1.y, qg8);

            unsigned ah[4], al[4];
            split2(x0, ah[0], al[0]);
            split2(x1, ah[1], al[1]);
            split2(x2, ah[2], al[2]);
            split2(x3, ah[3], al[3]);

            const int ku = k16 * 8 + t;
            #pragma unroll
            for (int nf = 0; nf < 8; nf++) {
                const char* rh = vsh + (nf * 8 + g) * (VS_STRIDE * 2);
                const char* rl = vsl + (nf * 8 + g) * (VS_STRIDE * 2);
                unsigned bh0 = *(const unsigned*)(rh + ku * 4);
                unsigned bh1 = *(const unsigned*)(rh + (ku + 4) * 4);
                unsigned bl0 = *(const unsigned*)(rl + ku * 4);
                unsigned bl1 = *(const unsigned*)(rl + (ku + 4) * 4);
                mma16816(acc[nf], ah, bh0, bh1);
                mma16816(acc[nf], ah, bl0, bl1);
                mma16816(acc[nf], al, bh0, bh1);
            }
        }
    };

    // prologue
    ldx(0, xra);
    load_chunk(0, 0);

    // manual 2x unroll: compute c from one reg-buffer while c+1's LDGs fill the other
    #pragma unroll 1
    for (int cc = 0; cc < NCH; cc += 2) {
        // even chunk cc (stage 0, frags xra); prefetch cc+1 -> xrb
        ldx(cc + 1, xrb);
        load_chunk(cc + 1, 1);
        asm volatile("cp.async.wait_group 1;");
        __syncthreads();
        compute_chunk(cc, 0, xra);
        __syncthreads();

        // odd chunk cc+1 (stage 1, frags xrb); prefetch cc+2 -> xra
        if (cc + 2 < NCH) {
            ldx(cc + 2, xra);
            load_chunk(cc + 2, 0);
            asm volatile("cp.async.wait_group 1;");
        } else {
            asm volatile("cp.async.wait_group 0;");
        }
        __syncthreads();
        compute_chunk(cc + 1, 1, xrb);
        __syncthreads();
    }

    // epilogue
    float sg = 0.f, sg8 = 0.f;
    #pragma unroll
    for (int nf = 0; nf < 8; nf++) {
        sg  = fmaf(acc[nf][0], acc[nf][0], sg);
        sg  = fmaf(acc[nf][1], acc[nf][1], sg);
        sg8 = fmaf(acc[nf][2], acc[nf][2], sg8);
        sg8 = fmaf(acc[nf][3], acc[nf][3], sg8);
    }
    sg  += __shfl_xor_sync(0xffffffffu, sg, 1);
    sg  += __shfl_xor_sync(0xffffffffu, sg, 2);
    sg8 += __shfl_xor_sync(0xffffffffu, sg8, 1);
    sg8 += __shfl_xor_sync(0xffffffffu, sg8, 2);
    qg  += __shfl_xor_sync(0xffffffffu, qg, 1);
    qg  += __shfl_xor_sync(0xffffffffu, qg, 2);
    qg8 += __shfl_xor_sync(0xffffffffu, qg8, 1);
    qg8 += __shfl_xor_sync(0xffffffffu, qg8, 2);
    if (t == 0) {
        out[row0w + g]     = 0.5f * (sg - qg);
        out[row0w + g + 8] = 0.5f * (sg8 - qg8);
    }
}

extern "C" void kernel_launch(void* const* d_in, const int* in_sizes, int n_in,
                              void* d_out, int out_size) {
    const float* x = (const float*)d_in[0];
    const float* v = (const float*)d_in[1];
    float* out = (float*)d_out;
    const int B = in_sizes[0] / XDIM;   // 16384

    prep_tc<<<XDIM / 64, 256>>>(v);

    cudaFuncSetAttribute(fm_mma, cudaFuncAttributeMaxDynamicSharedMemorySize, SMEM_BYTES);
    fm_mma<<<B / ROWS, THREADS, SMEM_BYTES>>>(x, out);
}

// round 8
// speedup vs baseline: 1.3539x; 1.3539x over previous
#include <cuda_runtime.h>
#include <cuda_bf16.h>
#include <cstdint>

#define XDIM 1024
#define KD 64            // output dim (N)
#define KC 64            // k-chunk
#define NCH (XDIM / KC)  // 16
#define ROWS 64
#define THREADS 128

#define VS_STRIDE 72                        // bf16 units per n-row (pad 64->72)
#define VS_BYTES (KD * VS_STRIDE * 2)       // 9216 per (hi|lo) tile
#define STAGE_BYTES (2 * VS_BYTES)          // 18432
#define OFF_W 0
#define OFF_V 4096
#define SMEM_BYTES (OFF_V + 2 * STAGE_BYTES)   // 40960 -> 4 CTAs/SM (reg-capped)

__device__ float g_w[XDIM];                               // w[i] = sum_k V[i][k]^2
__device__ __align__(16) unsigned short g_vth[KD * XDIM]; // vT_hi[n][i]
__device__ __align__(16) unsigned short g_vtl[KD * XDIM]; // vT_lo[n][i]

__device__ __forceinline__ unsigned smaddr(const void* p) {
    return (unsigned)__cvta_generic_to_shared(p);
}
__device__ __forceinline__ void cp16(unsigned dst, const void* src) {
    asm volatile("cp.async.cg.shared.global [%0], [%1], 16;" :: "r"(dst), "l"(src));
}
__device__ __forceinline__ unsigned packbf(float a, float b) {
    unsigned short ha = __bfloat16_as_ushort(__float2bfloat16(a));
    unsigned short hb = __bfloat16_as_ushort(__float2bfloat16(b));
    return (unsigned)ha | ((unsigned)hb << 16);
}
__device__ __forceinline__ void split2(float2 f, unsigned& hi, unsigned& lo) {
    __nv_bfloat16 hx = __float2bfloat16(f.x);
    __nv_bfloat16 hy = __float2bfloat16(f.y);
    hi = (unsigned)__bfloat16_as_ushort(hx) | ((unsigned)__bfloat16_as_ushort(hy) << 16);
    lo = packbf(f.x - __bfloat162float(hx), f.y - __bfloat162float(hy));
}
__device__ __forceinline__ void mma16816(float* d, const unsigned* a,
                                         unsigned b0, unsigned b1) {
    asm volatile(
        "mma.sync.aligned.m16n8k16.row.col.f32.bf16.bf16.f32 "
        "{%0,%1,%2,%3}, {%4,%5,%6,%7}, {%8,%9}, {%0,%1,%2,%3};"
        : "+f"(d[0]), "+f"(d[1]), "+f"(d[2]), "+f"(d[3])
        : "r"(a[0]), "r"(a[1]), "r"(a[2]), "r"(a[3]), "r"(b0), "r"(b1));
}
__device__ __forceinline__ void split1(float f, unsigned short& hh, unsigned short& ll) {
    __nv_bfloat16 bh = __float2bfloat16(f);
    hh = __bfloat16_as_ushort(bh);
    ll = __bfloat16_as_ushort(__float2bfloat16(f - __bfloat162float(bh)));
}

// ---------------- prep: transpose + split V, compute w ----------------
__global__ void prep_tc(const float* __restrict__ v) {
    __shared__ unsigned short th[KD][72];
    __shared__ unsigned short tl[KD][72];
    const int b = blockIdx.x;               // 16 blocks, i0 = b*64
    const int t = threadIdx.x;              // 256
    const int il = t >> 2, cq = t & 3;
    const int i = b * 64 + il;

    float wq = 0.f;
    #pragma unroll
    for (int j = 0; j < 4; j++) {
        float4 f = *(const float4*)(v + (size_t)i * KD + cq * 16 + j * 4);
        wq = fmaf(f.x, f.x, wq); wq = fmaf(f.y, f.y, wq);
        wq = fmaf(f.z, f.z, wq); wq = fmaf(f.w, f.w, wq);
        float vals[4] = {f.x, f.y, f.z, f.w};
        #pragma unroll
        for (int u = 0; u < 4; u++) {
            int n = cq * 16 + j * 4 + u;
            split1(vals[u], th[n][il], tl[n][il]);
        }
    }
    wq += __shfl_xor_sync(0xffffffffu, wq, 1);
    wq += __shfl_xor_sync(0xffffffffu, wq, 2);
    if (cq == 0) g_w[i] = wq;
    __syncthreads();

    const int n = t >> 2, un = t & 3;
    #pragma unroll
    for (int rr = 0; rr < 2; rr++) {
        int u = un + rr * 4;
        const unsigned short* ph = &th[n][u * 8];
        const unsigned short* pl = &tl[n][u * 8];
        uint4 oh, ol;
        oh.x = (unsigned)ph[0] | ((unsigned)ph[1] << 16);
        oh.y = (unsigned)ph[2] | ((unsigned)ph[3] << 16);
        oh.z = (unsigned)ph[4] | ((unsigned)ph[5] << 16);
        oh.w = (unsigned)ph[6] | ((unsigned)ph[7] << 16);
        ol.x = (unsigned)pl[0] | ((unsigned)pl[1] << 16);
        ol.y = (unsigned)pl[2] | ((unsigned)pl[3] << 16);
        ol.z = (unsigned)pl[4] | ((unsigned)pl[5] << 16);
        ol.w = (unsigned)pl[6] | ((unsigned)pl[7] << 16);
        *(uint4*)(g_vth + (size_t)n * XDIM + b * 64 + u * 8) = oh;
        *(uint4*)(g_vtl + (size_t)n * XDIM + b * 64 + u * 8) = ol;
    }
}

// ---------------- main: split-bf16 mma.sync GEMM, 4 CTAs/SM ----------------
__global__ __launch_bounds__(THREADS, 4)
void fm_mma(const float* __restrict__ x, float* __restrict__ out) {
    extern __shared__ __align__(128) char smem[];
    const unsigned sbase = smaddr(smem);
    const int tid = threadIdx.x;
    const int warp = tid >> 5;        // 0..3
    const int lane = tid & 31;
    const int g = lane >> 2;
    const int t = lane & 3;
    const size_t row0w = (size_t)blockIdx.x * ROWS + warp * 16;

    // stage w (1024 floats, 128 threads -> 2 float4 each)
    *(float4*)(smem + OFF_W + tid * 16) = *(const float4*)(g_w + tid * 4);
    *(float4*)(smem + OFF_W + (tid + THREADS) * 16) =
        *(const float4*)(g_w + (tid + THREADS) * 4);

    float acc[8][4];
    #pragma unroll
    for (int nf = 0; nf < 8; nf++)
        #pragma unroll
        for (int j = 0; j < 4; j++) acc[nf][j] = 0.f;
    float qg = 0.f, qg8 = 0.f;

    auto load_chunk = [&](int c, int s) {
        unsigned vh = sbase + OFF_V + s * STAGE_BYTES;
        unsigned vl = vh + VS_BYTES;
        // hi: 512 16B units (64 rows x 8), lo: 512 more; 128 threads -> 4 each
        #pragma unroll
        for (int nn = 0; nn < 4; nn++) {
            int u = tid + nn * THREADS;
            int row = u >> 3, o = u & 7;
            cp16(vh + row * (VS_STRIDE * 2) + o * 16,
                 g_vth + (size_t)row * XDIM + c * KC + o * 8);
        }
        #pragma unroll
        for (int nn = 0; nn < 4; nn++) {
            int u = tid + nn * THREADS;
            int row = u >> 3, o = u & 7;
            cp16(vl + row * (VS_STRIDE * 2) + o * 16,
                 g_vtl + (size_t)row * XDIM + c * KC + o * 8);
        }
        asm volatile("cp.async.commit_group;");
    };

    auto compute_chunk = [&](int c, int s) {
        const char* vsh = smem + OFF_V + s * STAGE_BYTES;
        const char* vsl = vsh + VS_BYTES;
        const float* wsm = (const float*)(smem + OFF_W) + c * KC;
        const float* xg  = x + row0w * XDIM + c * KC;

        // this chunk's x fragments (16 float2, MLP 16)
        float2 xr[16];
        #pragma unroll
        for (int k16 = 0; k16 < 4; k16++) {
            const float* p = xg + k16 * 16 + 2 * t;
            xr[k16 * 4 + 0] = *(const float2*)(p + (size_t)g * XDIM);
            xr[k16 * 4 + 1] = *(const float2*)(p + (size_t)(g + 8) * XDIM);
            xr[k16 * 4 + 2] = *(const float2*)(p + (size_t)g * XDIM + 8);
            xr[k16 * 4 + 3] = *(const float2*)(p + (size_t)(g + 8) * XDIM + 8);
        }
        #pragma unroll
        for (int k16 = 0; k16 < 4; k16++) {
            float2 x0 = xr[k16 * 4 + 0], x1 = xr[k16 * 4 + 1];
            float2 x2 = xr[k16 * 4 + 2], x3 = xr[k16 * 4 + 3];
            float2 w0 = *(const float2*)(wsm + k16 * 16 + 2 * t);
            float2 w1 = *(const float2*)(wsm + k16 * 16 + 2 * t + 8);
            qg  = fmaf(x0.x * x0.x, w0.x, qg);
            qg  = fmaf(x0.y * x0.y, w0.y, qg);
            qg  = fmaf(x2.x * x2.x, w1.x, qg);
            qg  = fmaf(x2.y * x2.y, w1.y, qg);
            qg8 = fmaf(x1.x * x1.x, w0.x, qg8);
            qg8 = fmaf(x1.y * x1.y, w0.y, qg8);
            qg8 = fmaf(x3.x * x3.x, w1.x, qg8);
            qg8 = fmaf(x3.y * x3.y, w1.y, qg8);

            unsigned ah[4], al[4];
            split2(x0, ah[0], al[0]);
            split2(x1, ah[1], al[1]);
            split2(x2, ah[2], al[2]);
            split2(x3, ah[3], al[3]);

            const int ku = k16 * 8 + t;
            #pragma unroll
            for (int nf = 0; nf < 8; nf++) {
                const char* rh = vsh + (nf * 8 + g) * (VS_STRIDE * 2);
                const char* rl = vsl + (nf * 8 + g) * (VS_STRIDE * 2);
                unsigned bh0 = *(const unsigned*)(rh + ku * 4);
                unsigned bh1 = *(const unsigned*)(rh + (ku + 4) * 4);
                unsigned bl0 = *(const unsigned*)(rl + ku * 4);
                unsigned bl1 = *(const unsigned*)(rl + (ku + 4) * 4);
                mma16816(acc[nf], ah, bh0, bh1);
                mma16816(acc[nf], ah, bl0, bl1);
                mma16816(acc[nf], al, bh0, bh1);
            }
        }
    };

    load_chunk(0, 0);
    for (int c = 0; c < NCH; c++) {
        if (c + 1 < NCH) {
            load_chunk(c + 1, (c + 1) & 1);
            asm volatile("cp.async.wait_group 1;");
        } else {
            asm volatile("cp.async.wait_group 0;");
        }
        __syncthreads();
        compute_chunk(c, c & 1);
        __syncthreads();
    }

    // epilogue: sum y^2 per row, reduce over t lanes, subtract q
    float sg = 0.f, sg8 = 0.f;
    #pragma unroll
    for (int nf = 0; nf < 8; nf++) {
        sg  = fmaf(acc[nf][0], acc[nf][0], sg);
        sg  = fmaf(acc[nf][1], acc[nf][1], sg);
        sg8 = fmaf(acc[nf][2], acc[nf][2], sg8);
        sg8 = fmaf(acc[nf][3], acc[nf][3], sg8);
    }
    sg  += __shfl_xor_sync(0xffffffffu, sg, 1);
    sg  += __shfl_xor_sync(0xffffffffu, sg, 2);
    sg8 += __shfl_xor_sync(0xffffffffu, sg8, 1);
    sg8 += __shfl_xor_sync(0xffffffffu, sg8, 2);
    qg  += __shfl_xor_sync(0xffffffffu, qg, 1);
    qg  += __shfl_xor_sync(0xffffffffu, qg, 2);
    qg8 += __shfl_xor_sync(0xffffffffu, qg8, 1);
    qg8 += __shfl_xor_sync(0xffffffffu, qg8, 2);
    if (t == 0) {
        out[row0w + g]     = 0.5f * (sg - qg);
        out[row0w + g + 8] = 0.5f * (sg8 - qg8);
    }
}

extern "C" void kernel_launch(void* const* d_in, const int* in_sizes, int n_in,
                              void* d_out, int out_size) {
    const float* x = (const float*)d_in[0];
    const float* v = (const float*)d_in[1];
    float* out = (float*)d_out;
    const int B = in_sizes[0] / XDIM;   // 16384

    prep_tc<<<XDIM / 64, 256>>>(v);

    cudaFuncSetAttribute(fm_mma, cudaFuncAttributeMaxDynamicSharedMemorySize, SMEM_BYTES);
    fm_mma<<<B / ROWS, THREADS, SMEM_BYTES>>>(x, out);
}

// round 9
// speedup vs baseline: 1.4256x; 1.0530x over previous
#include <cuda_runtime.h>
#include <cuda_bf16.h>
#include <cstdint>

#define XDIM 1024
#define KD 64            // output dim (N)
#define KC 64            // k-chunk
#define NCH (XDIM / KC)  // 16
#define ROWS 64
#define THREADS 128
#define NSTAGE 3

#define XS_STRIDE 68                        // floats per x row (pad 64->68) -> <=2-way LDS
#define XS_BYTES (ROWS * XS_STRIDE * 4)     // 17408
#define VS_STRIDE 72                        // bf16 units per n-row (pad 64->72)
#define VS_BYTES (KD * VS_STRIDE * 2)       // 9216 per (hi|lo) tile
#define STAGE_BYTES (XS_BYTES + 2 * VS_BYTES)  // 35840
#define OFF_W 0
#define OFF_S 4096
#define SMEM_BYTES (OFF_S + NSTAGE * STAGE_BYTES)   // 111616 -> 2 CTAs/SM

__device__ float g_w[XDIM];                               // w[i] = sum_k V[i][k]^2
__device__ __align__(16) unsigned short g_vth[KD * XDIM]; // vT_hi[n][i]
__device__ __align__(16) unsigned short g_vtl[KD * XDIM]; // vT_lo[n][i]

__device__ __forceinline__ unsigned smaddr(const void* p) {
    return (unsigned)__cvta_generic_to_shared(p);
}
__device__ __forceinline__ void cp16(unsigned dst, const void* src) {
    asm volatile("cp.async.cg.shared.global [%0], [%1], 16;" :: "r"(dst), "l"(src));
}
__device__ __forceinline__ unsigned packbf(float a, float b) {
    unsigned short ha = __bfloat16_as_ushort(__float2bfloat16(a));
    unsigned short hb = __bfloat16_as_ushort(__float2bfloat16(b));
    return (unsigned)ha | ((unsigned)hb << 16);
}
__device__ __forceinline__ void split2(float2 f, unsigned& hi, unsigned& lo) {
    __nv_bfloat16 hx = __float2bfloat16(f.x);
    __nv_bfloat16 hy = __float2bfloat16(f.y);
    hi = (unsigned)__bfloat16_as_ushort(hx) | ((unsigned)__bfloat16_as_ushort(hy) << 16);
    lo = packbf(f.x - __bfloat162float(hx), f.y - __bfloat162float(hy));
}
__device__ __forceinline__ void mma16816(float* d, const unsigned* a,
                                         unsigned b0, unsigned b1) {
    asm volatile(
        "mma.sync.aligned.m16n8k16.row.col.f32.bf16.bf16.f32 "
        "{%0,%1,%2,%3}, {%4,%5,%6,%7}, {%8,%9}, {%0,%1,%2,%3};"
        : "+f"(d[0]), "+f"(d[1]), "+f"(d[2]), "+f"(d[3])
        : "r"(a[0]), "r"(a[1]), "r"(a[2]), "r"(a[3]), "r"(b0), "r"(b1));
}
__device__ __forceinline__ void split1(float f, unsigned short& hh, unsigned short& ll) {
    __nv_bfloat16 bh = __float2bfloat16(f);
    hh = __bfloat16_as_ushort(bh);
    ll = __bfloat16_as_ushort(__float2bfloat16(f - __bfloat162float(bh)));
}

// ---------------- prep: transpose + split V, compute w ----------------
__global__ void prep_tc(const float* __restrict__ v) {
    __shared__ unsigned short th[KD][72];
    __shared__ unsigned short tl[KD][72];
    const int b = blockIdx.x;               // 16 blocks, i0 = b*64
    const int t = threadIdx.x;              // 256
    const int il = t >> 2, cq = t & 3;
    const int i = b * 64 + il;

    float wq = 0.f;
    #pragma unroll
    for (int j = 0; j < 4; j++) {
        float4 f = *(const float4*)(v + (size_t)i * KD + cq * 16 + j * 4);
        wq = fmaf(f.x, f.x, wq); wq = fmaf(f.y, f.y, wq);
        wq = fmaf(f.z, f.z, wq); wq = fmaf(f.w, f.w, wq);
        float vals[4] = {f.x, f.y, f.z, f.w};
        #pragma unroll
        for (int u = 0; u < 4; u++) {
            int n = cq * 16 + j * 4 + u;
            split1(vals[u], th[n][il], tl[n][il]);
        }
    }
    wq += __shfl_xor_sync(0xffffffffu, wq, 1);
    wq += __shfl_xor_sync(0xffffffffu, wq, 2);
    if (cq == 0) g_w[i] = wq;
    __syncthreads();

    const int n = t >> 2, un = t & 3;
    #pragma unroll
    for (int rr = 0; rr < 2; rr++) {
        int u = un + rr * 4;
        const unsigned short* ph = &th[n][u * 8];
        const unsigned short* pl = &tl[n][u * 8];
        uint4 oh, ol;
        oh.x = (unsigned)ph[0] | ((unsigned)ph[1] << 16);
        oh.y = (unsigned)ph[2] | ((unsigned)ph[3] << 16);
        oh.z = (unsigned)ph[4] | ((unsigned)ph[5] << 16);
        oh.w = (unsigned)ph[6] | ((unsigned)ph[7] << 16);
        ol.x = (unsigned)pl[0] | ((unsigned)pl[1] << 16);
        ol.y = (unsigned)pl[2] | ((unsigned)pl[3] << 16);
        ol.z = (unsigned)pl[4] | ((unsigned)pl[5] << 16);
        ol.w = (unsigned)pl[6] | ((unsigned)pl[7] << 16);
        *(uint4*)(g_vth + (size_t)n * XDIM + b * 64 + u * 8) = oh;
        *(uint4*)(g_vtl + (size_t)n * XDIM + b * 64 + u * 8) = ol;
    }
}

// ---------------- main: split-bf16 mma.sync, x+V 3-stage cp.async pipeline ----------------
__global__ __launch_bounds__(THREADS, 2)
void fm_mma(const float* __restrict__ x, float* __restrict__ out) {
    extern __shared__ __align__(128) char smem[];
    const unsigned sbase = smaddr(smem);
    const int tid = threadIdx.x;
    const int warp = tid >> 5;        // 0..3
    const int lane = tid & 31;
    const int g = lane >> 2;
    const int t = lane & 3;
    const size_t row0 = (size_t)blockIdx.x * ROWS;

    // stage w (1024 floats, 128 threads -> 2 float4 each)
    *(float4*)(smem + OFF_W + tid * 16) = *(const float4*)(g_w + tid * 4);
    *(float4*)(smem + OFF_W + (tid + THREADS) * 16) =
        *(const float4*)(g_w + (tid + THREADS) * 4);

    float acc[8][4];
    #pragma unroll
    for (int nf = 0; nf < 8; nf++)
        #pragma unroll
        for (int j = 0; j < 4; j++) acc[nf][j] = 0.f;
    float qg = 0.f, qg8 = 0.f;

    auto load_chunk = [&](int c, int s) {
        unsigned st = sbase + OFF_S + s * STAGE_BYTES;
        unsigned xsm = st;
        unsigned vh = st + XS_BYTES;
        unsigned vl = vh + VS_BYTES;
        // x tile: 64 rows x 64 floats = 1024 float4 -> 8 cp16 per thread
        #pragma unroll
        for (int nn = 0; nn < 8; nn++) {
            int u = tid + nn * THREADS;
            int r = u >> 4, cc = u & 15;
            cp16(xsm + r * (XS_STRIDE * 4) + cc * 16,
                 x + (row0 + r) * XDIM + c * KC + cc * 4);
        }
        // V hi/lo: 512 16B units each -> 4+4 cp16 per thread
        #pragma unroll
        for (int nn = 0; nn < 4; nn++) {
            int u = tid + nn * THREADS;
            int row = u >> 3, o = u & 7;
            cp16(vh + row * (VS_STRIDE * 2) + o * 16,
                 g_vth + (size_t)row * XDIM + c * KC + o * 8);
        }
        #pragma unroll
        for (int nn = 0; nn < 4; nn++) {
            int u = tid + nn * THREADS;
            int row = u >> 3, o = u & 7;
            cp16(vl + row * (VS_STRIDE * 2) + o * 16,
                 g_vtl + (size_t)row * XDIM + c * KC + o * 8);
        }
        asm volatile("cp.async.commit_group;");
    };

    auto compute_chunk = [&](int c, int s) {
        const char* st = smem + OFF_S + s * STAGE_BYTES;
        const float* xsm = (const float*)st;
        const char* vsh = st + XS_BYTES;
        const char* vsl = vsh + VS_BYTES;
        const float* wsm = (const float*)(smem + OFF_W) + c * KC;

        // x fragments from smem (LDS, latency trivially hidden)
        float2 xr[16];
        #pragma unroll
        for (int k16 = 0; k16 < 4; k16++) {
            const float* p = xsm + k16 * 16 + 2 * t;
            const float* r0 = p + (warp * 16 + g) * XS_STRIDE;
            const float* r8 = p + (warp * 16 + g + 8) * XS_STRIDE;
            xr[k16 * 4 + 0] = *(const float2*)(r0);
            xr[k16 * 4 + 1] = *(const float2*)(r8);
            xr[k16 * 4 + 2] = *(const float2*)(r0 + 8);
            xr[k16 * 4 + 3] = *(const float2*)(r8 + 8);
        }
        #pragma unroll
        for (int k16 = 0; k16 < 4; k16++) {
            float2 x0 = xr[k16 * 4 + 0], x1 = xr[k16 * 4 + 1];
            float2 x2 = xr[k16 * 4 + 2], x3 = xr[k16 * 4 + 3];
            float2 w0 = *(const float2*)(wsm + k16 * 16 + 2 * t);
            float2 w1 = *(const float2*)(wsm + k16 * 16 + 2 * t + 8);
            qg  = fmaf(x0.x * x0.x, w0.x, qg);
            qg  = fmaf(x0.y * x0.y, w0.y, qg);
            qg  = fmaf(x2.x * x2.x, w1.x, qg);
            qg  = fmaf(x2.y * x2.y, w1.y, qg);
            qg8 = fmaf(x1.x * x1.x, w0.x, qg8);
            qg8 = fmaf(x1.y * x1.y, w0.y, qg8);
            qg8 = fmaf(x3.x * x3.x, w1.x, qg8);
            qg8 = fmaf(x3.y * x3.y, w1.y, qg8);

            unsigned ah[4], al[4];
            split2(x0, ah[0], al[0]);
            split2(x1, ah[1], al[1]);
            split2(x2, ah[2], al[2]);
            split2(x3, ah[3], al[3]);

            const int ku = k16 * 8 + t;
            #pragma unroll
            for (int nf = 0; nf < 8; nf++) {
                const char* rh = vsh + (nf * 8 + g) * (VS_STRIDE * 2);
                const char* rl = vsl + (nf * 8 + g) * (VS_STRIDE * 2);
                unsigned bh0 = *(const unsigned*)(rh + ku * 4);
                unsigned bh1 = *(const unsigned*)(rh + (ku + 4) * 4);
                unsigned bl0 = *(const unsigned*)(rl + ku * 4);
                unsigned bl1 = *(const unsigned*)(rl + (ku + 4) * 4);
                mma16816(acc[nf], ah, bh0, bh1);
                mma16816(acc[nf], ah, bl0, bl1);
                mma16816(acc[nf], al, bh0, bh1);
            }
        }
    };

    // prologue: prime two stages
    load_chunk(0, 0);
    load_chunk(1, 1);

    #pragma unroll 1
    for (int c = 0; c < NCH; c++) {
        __syncthreads();   // compute(c-1) done before load(c+2) reuses its stage
        if (c + 2 < NCH) {
            load_chunk(c + 2, (c + 2) % NSTAGE);
            asm volatile("cp.async.wait_group 2;");
        } else if (c + 1 < NCH) {
            asm volatile("cp.async.wait_group 1;");
        } else {
            asm volatile("cp.async.wait_group 0;");
        }
        compute_chunk(c, c % NSTAGE);
    }

    // epilogue: sum y^2 per row, reduce over t lanes, subtract q
    float sg = 0.f, sg8 = 0.f;
    #pragma unroll
    for (int nf = 0; nf < 8; nf++) {
        sg  = fmaf(acc[nf][0], acc[nf][0], sg);
        sg  = fmaf(acc[nf][1], acc[nf][1], sg);
        sg8 = fmaf(acc[nf][2], acc[nf][2], sg8);
        sg8 = fmaf(acc[nf][3], acc[nf][3], sg8);
    }
    sg  += __shfl_xor_sync(0xffffffffu, sg, 1);
    sg  += __shfl_xor_sync(0xffffffffu, sg, 2);
    sg8 += __shfl_xor_sync(0xffffffffu, sg8, 1);
    sg8 += __shfl_xor_sync(0xffffffffu, sg8, 2);
    qg  += __shfl_xor_sync(0xffffffffu, qg, 1);
    qg  += __shfl_xor_sync(0xffffffffu, qg, 2);
    qg8 += __shfl_xor_sync(0xffffffffu, qg8, 1);
    qg8 += __shfl_xor_sync(0xffffffffu, qg8, 2);
    if (t == 0) {
        out[row0 + warp * 16 + g]     = 0.5f * (sg - qg);
        out[row0 + warp * 16 + g + 8] = 0.5f * (sg8 - qg8);
    }
}

extern "C" void kernel_launch(void* const* d_in, const int* in_sizes, int n_in,
                              void* d_out, int out_size) {
    const float* x = (const float*)d_in[0];
    const float* v = (const float*)d_in[1];
    float* out = (float*)d_out;
    const int B = in_sizes[0] / XDIM;   // 16384

    prep_tc<<<XDIM / 64, 256>>>(v);

    cudaFuncSetAttribute(fm_mma, cudaFuncAttributeMaxDynamicSharedMemorySize, SMEM_BYTES);
    fm_mma<<<B / ROWS, THREADS, SMEM_BYTES>>>(x, out);
}